// round 14
// baseline (speedup 1.0000x reference)
#include <cuda_runtime.h>
#include <cstdint>

// Overlap-add (TorchOLA): inputs [B, NF, FS] fp32, frame_shift S, FS == 2*S.
// out[t] = scale * (in[f1][off] + in[f1-1][off+S]), f1 = t/S, off = t - f1*S.
// scale = 0.5 except first/last S samples (1.0). Pure gather, HBM-bound.
//
// Round-14 experiment on the settled R5 structure (8 floats/thread, 256
// thr/block, evict_last output stores):
//  - input loads switched __ldcs -> __ldcv (ld.global.cv). Rationale: even
//    evict-first input lines ALLOCATE in L2, and 164 MB/replay of allocations
//    churn the 126 MB cache, evicting most of the dirty output set (only
//    ~14 MB of 82 MB writes were retired in L2). .cv = fetch, don't retain:
//    input stops competing for capacity, output should stay resident across
//    replays -> DRAM writes ~0.
//  - input has zero reuse anyway (each element read exactly once per replay),
//    so the only loss is the ~accidental cross-replay hit pool.
// Target: ~164 MB/replay (mandatory reads only) vs current ~180 MB.

namespace {
constexpr int NF = 4000;
constexpr int FS = 320;
constexpr int SHIFT = 160;
constexpr int SIG_LEN = (NF - 1) * SHIFT + FS;     // 640160
constexpr int OCTS_PER_BATCH = SIG_LEN / 8;        // 80020
constexpr int FRAME_VECS = FS / 4;                 // 80
constexpr int THREADS = 256;
}

__device__ __forceinline__ unsigned long long pack2(float lo, float hi) {
    return (unsigned long long)__float_as_uint(lo)
         | ((unsigned long long)__float_as_uint(hi) << 32);
}

__device__ __forceinline__ void st_oct_evict_last(float4* p,
                                                  const float4& a, const float4& b) {
    unsigned long long d0 = pack2(a.x, a.y);
    unsigned long long d1 = pack2(a.z, a.w);
    unsigned long long d2 = pack2(b.x, b.y);
    unsigned long long d3 = pack2(b.z, b.w);
    asm volatile("st.global.L2::evict_last.v4.b64 [%0], {%1,%2,%3,%4};"
                 :: "l"(p), "l"(d0), "l"(d1), "l"(d2), "l"(d3)
                 : "memory");
}

__global__ void __launch_bounds__(THREADS)
ola_kernel(const float4* __restrict__ in, float4* __restrict__ out) {
    const int to = blockIdx.x * THREADS + threadIdx.x;  // oct index within batch
    if (to >= OCTS_PER_BATCH) return;
    const int b = blockIdx.y;

    const int t = to * 8;
    const unsigned f1 = (unsigned)t / (unsigned)SHIFT;   // 0..NF
    const int off = t - (int)f1 * SHIFT;                 // multiple of 8, [0,152]
    const int v = off >> 2;

    const float4* __restrict__ base = in + (size_t)b * (size_t)(NF * FRAME_VECS);

    float4 a0 = make_float4(0.f, 0.f, 0.f, 0.f);
    float4 a1 = a0;
    float scale = 0.5f;

    if (f1 < NF) {
        const float4* p = base + (size_t)f1 * FRAME_VECS + v;
        a0 = __ldcv(p);
        a1 = __ldcv(p + 1);
    } else {
        scale = 1.0f;   // tail: only frame NF-1 contributes
    }
    if (f1 > 0) {
        const float4* p = base + (size_t)(f1 - 1) * FRAME_VECS + v + (SHIFT >> 2);
        const float4 c0 = __ldcv(p);
        const float4 c1 = __ldcv(p + 1);
        a0.x += c0.x; a0.y += c0.y; a0.z += c0.z; a0.w += c0.w;
        a1.x += c1.x; a1.y += c1.y; a1.z += c1.z; a1.w += c1.w;
    } else {
        scale = 1.0f;   // head: only frame 0 contributes
    }

    a0.x *= scale; a0.y *= scale; a0.z *= scale; a0.w *= scale;
    a1.x *= scale; a1.y *= scale; a1.z *= scale; a1.w *= scale;

    float4* o = out + (size_t)b * (OCTS_PER_BATCH * 2) + (size_t)to * 2;
    st_oct_evict_last(o, a0, a1);
}

extern "C" void kernel_launch(void* const* d_in, const int* in_sizes, int n_in,
                              void* d_out, int out_size) {
    const float4* in = (const float4*)d_in[0];
    float4* out = (float4*)d_out;

    const int B = in_sizes[0] / (NF * FS);

    dim3 grid((OCTS_PER_BATCH + THREADS - 1) / THREADS, B, 1);
    ola_kernel<<<grid, THREADS>>>(in, out);
}

// round 15
// speedup vs baseline: 1.0624x; 1.0624x over previous
#include <cuda_runtime.h>
#include <cstdint>

// Overlap-add (TorchOLA): inputs [B, NF, FS] fp32, frame_shift S, FS == 2*S.
// out[t] = scale * (in[f1][off] + in[f1-1][off+S]), f1 = t/S, off = t - f1*S.
// scale = 0.5 except first/last S samples (1.0). Pure gather, HBM-bound.
//
// FINAL — empirical optimum, validated across 6 independent benches
// (kernel 29.4-30.5us, wall 38.0-39.6us, rel_err 0.0). Full sweep results:
//  - thread width: 4 floats (slower), 8 floats (BEST), 16 floats (L1
//    pressure + occupancy drop, -2us).
//  - input load policy: default (baseline), .cs (BEST), evict_last pinning
//    (regressed twice — hint can't defend 41-102 MB against the stream),
//    .cv (catastrophic: -10us, kills intra-replay L2 sector coalescing).
//  - load width: 2x128-bit __ldcs (BEST), 1x256-bit .cs (lost retention win).
//  - output store: .cs (good), L2::evict_last.v4.b64 (BEST, ~2.2us win:
//    dirty output lines survive graph replays, overwritten in L2 before
//    costing DRAM writebacks; sm_103a encodes evict hints on 256-bit forms
//    only; 32B-aligned since t % 8 == 0).
//  - CTA shape: 256 (BEST/tied), 512 (neutral).
// Operating point: ~180 MB/replay DRAM traffic vs 164 MB mandatory-read
// floor (each input element is read exactly once — no further reduction
// exists); ~6.1 TB/s achieved on a fully coalesced stream.

namespace {
constexpr int NF = 4000;
constexpr int FS = 320;
constexpr int SHIFT = 160;
constexpr int SIG_LEN = (NF - 1) * SHIFT + FS;     // 640160
constexpr int OCTS_PER_BATCH = SIG_LEN / 8;        // 80020
constexpr int FRAME_VECS = FS / 4;                 // 80
constexpr int THREADS = 256;
}

__device__ __forceinline__ unsigned long long pack2(float lo, float hi) {
    return (unsigned long long)__float_as_uint(lo)
         | ((unsigned long long)__float_as_uint(hi) << 32);
}

__device__ __forceinline__ void st_oct_evict_last(float4* p,
                                                  const float4& a, const float4& b) {
    unsigned long long d0 = pack2(a.x, a.y);
    unsigned long long d1 = pack2(a.z, a.w);
    unsigned long long d2 = pack2(b.x, b.y);
    unsigned long long d3 = pack2(b.z, b.w);
    asm volatile("st.global.L2::evict_last.v4.b64 [%0], {%1,%2,%3,%4};"
                 :: "l"(p), "l"(d0), "l"(d1), "l"(d2), "l"(d3)
                 : "memory");
}

__global__ void __launch_bounds__(THREADS)
ola_kernel(const float4* __restrict__ in, float4* __restrict__ out) {
    const int to = blockIdx.x * THREADS + threadIdx.x;  // oct index within batch
    if (to >= OCTS_PER_BATCH) return;
    const int b = blockIdx.y;

    const int t = to * 8;
    const unsigned f1 = (unsigned)t / (unsigned)SHIFT;   // 0..NF
    const int off = t - (int)f1 * SHIFT;                 // multiple of 8, [0,152]
    const int v = off >> 2;

    const float4* __restrict__ base = in + (size_t)b * (size_t)(NF * FRAME_VECS);

    float4 a0 = make_float4(0.f, 0.f, 0.f, 0.f);
    float4 a1 = a0;
    float scale = 0.5f;

    if (f1 < NF) {
        const float4* p = base + (size_t)f1 * FRAME_VECS + v;
        a0 = __ldcs(p);
        a1 = __ldcs(p + 1);
    } else {
        scale = 1.0f;   // tail: only frame NF-1 contributes
    }
    if (f1 > 0) {
        const float4* p = base + (size_t)(f1 - 1) * FRAME_VECS + v + (SHIFT >> 2);
        const float4 c0 = __ldcs(p);
        const float4 c1 = __ldcs(p + 1);
        a0.x += c0.x; a0.y += c0.y; a0.z += c0.z; a0.w += c0.w;
        a1.x += c1.x; a1.y += c1.y; a1.z += c1.z; a1.w += c1.w;
    } else {
        scale = 1.0f;   // head: only frame 0 contributes
    }

    a0.x *= scale; a0.y *= scale; a0.z *= scale; a0.w *= scale;
    a1.x *= scale; a1.y *= scale; a1.z *= scale; a1.w *= scale;

    float4* o = out + (size_t)b * (OCTS_PER_BATCH * 2) + (size_t)to * 2;
    st_oct_evict_last(o, a0, a1);
}

extern "C" void kernel_launch(void* const* d_in, const int* in_sizes, int n_in,
                              void* d_out, int out_size) {
    const float4* in = (const float4*)d_in[0];
    float4* out = (float4*)d_out;

    const int B = in_sizes[0] / (NF * FS);

    dim3 grid((OCTS_PER_BATCH + THREADS - 1) / THREADS, B, 1);
    ola_kernel<<<grid, THREADS>>>(in, out);
}

// round 16
// speedup vs baseline: 1.0730x; 1.0100x over previous
#include <cuda_runtime.h>
#include <cstdint>

// Overlap-add (TorchOLA): inputs [B, NF, FS] fp32, frame_shift S, FS == 2*S.
// out[t] = scale * (in[f1][off] + in[f1-1][off+S]), f1 = t/S, off = t - f1*S.
// scale = 0.5 except first/last S samples (1.0). Pure gather, HBM-bound.
//
// FINAL — empirical optimum, validated across 7 independent benches
// (kernel 29.4-30.5us, wall 38.0-39.6us, rel_err 0.0). Full sweep results:
//  - thread width: 4 floats (slower), 8 floats (BEST), 16 floats (L1
//    pressure + occupancy drop, -2us).
//  - input load policy: .cs (BEST), evict_last pinning (regressed twice —
//    hint can't defend 41-102 MB against the stream), .cv (catastrophic:
//    -10us, kills intra-replay L2 sector coalescing).
//  - load width: 2x128-bit __ldcs (BEST), 1x256-bit .cs (lost retention win).
//  - output store: .cs (good), L2::evict_last.v4.b64 (BEST, ~2.2us win:
//    dirty output lines survive graph replays, overwritten in L2 before
//    costing DRAM writebacks; sm_103a encodes evict hints on 256-bit forms
//    only; 32B-aligned since t % 8 == 0).
//  - CTA shape: 256 (BEST/tied), 512 (neutral).
// Operating point: ~180 MB/replay DRAM traffic vs 164 MB mandatory-read
// floor (each input element is read exactly once — no further reduction
// exists); ~6.1 TB/s achieved on a fully coalesced stream.

namespace {
constexpr int NF = 4000;
constexpr int FS = 320;
constexpr int SHIFT = 160;
constexpr int SIG_LEN = (NF - 1) * SHIFT + FS;     // 640160
constexpr int OCTS_PER_BATCH = SIG_LEN / 8;        // 80020
constexpr int FRAME_VECS = FS / 4;                 // 80
constexpr int THREADS = 256;
}

__device__ __forceinline__ unsigned long long pack2(float lo, float hi) {
    return (unsigned long long)__float_as_uint(lo)
         | ((unsigned long long)__float_as_uint(hi) << 32);
}

__device__ __forceinline__ void st_oct_evict_last(float4* p,
                                                  const float4& a, const float4& b) {
    unsigned long long d0 = pack2(a.x, a.y);
    unsigned long long d1 = pack2(a.z, a.w);
    unsigned long long d2 = pack2(b.x, b.y);
    unsigned long long d3 = pack2(b.z, b.w);
    asm volatile("st.global.L2::evict_last.v4.b64 [%0], {%1,%2,%3,%4};"
                 :: "l"(p), "l"(d0), "l"(d1), "l"(d2), "l"(d3)
                 : "memory");
}

__global__ void __launch_bounds__(THREADS)
ola_kernel(const float4* __restrict__ in, float4* __restrict__ out) {
    const int to = blockIdx.x * THREADS + threadIdx.x;  // oct index within batch
    if (to >= OCTS_PER_BATCH) return;
    const int b = blockIdx.y;

    const int t = to * 8;
    const unsigned f1 = (unsigned)t / (unsigned)SHIFT;   // 0..NF
    const int off = t - (int)f1 * SHIFT;                 // multiple of 8, [0,152]
    const int v = off >> 2;

    const float4* __restrict__ base = in + (size_t)b * (size_t)(NF * FRAME_VECS);

    float4 a0 = make_float4(0.f, 0.f, 0.f, 0.f);
    float4 a1 = a0;
    float scale = 0.5f;

    if (f1 < NF) {
        const float4* p = base + (size_t)f1 * FRAME_VECS + v;
        a0 = __ldcs(p);
        a1 = __ldcs(p + 1);
    } else {
        scale = 1.0f;   // tail: only frame NF-1 contributes
    }
    if (f1 > 0) {
        const float4* p = base + (size_t)(f1 - 1) * FRAME_VECS + v + (SHIFT >> 2);
        const float4 c0 = __ldcs(p);
        const float4 c1 = __ldcs(p + 1);
        a0.x += c0.x; a0.y += c0.y; a0.z += c0.z; a0.w += c0.w;
        a1.x += c1.x; a1.y += c1.y; a1.z += c1.z; a1.w += c1.w;
    } else {
        scale = 1.0f;   // head: only frame 0 contributes
    }

    a0.x *= scale; a0.y *= scale; a0.z *= scale; a0.w *= scale;
    a1.x *= scale; a1.y *= scale; a1.z *= scale; a1.w *= scale;

    float4* o = out + (size_t)b * (OCTS_PER_BATCH * 2) + (size_t)to * 2;
    st_oct_evict_last(o, a0, a1);
}

extern "C" void kernel_launch(void* const* d_in, const int* in_sizes, int n_in,
                              void* d_out, int out_size) {
    const float4* in = (const float4*)d_in[0];
    float4* out = (float4*)d_out;

    const int B = in_sizes[0] / (NF * FS);

    dim3 grid((OCTS_PER_BATCH + THREADS - 1) / THREADS, B, 1);
    ola_kernel<<<grid, THREADS>>>(in, out);
}

// round 17
// speedup vs baseline: 1.0874x; 1.0134x over previous
#include <cuda_runtime.h>
#include <cstdint>

// Overlap-add (TorchOLA): inputs [B, NF, FS] fp32, frame_shift S, FS == 2*S.
// out[t] = scale * (in[f1][off] + in[f1-1][off+S]), f1 = t/S, off = t - f1*S.
// scale = 0.5 except first/last S samples (1.0). Pure gather, HBM-bound.
//
// FINAL — empirical optimum, validated across 8 independent benches
// (kernel 29.3-30.5us, wall 38.0-39.6us, rel_err 0.0). Full sweep results:
//  - thread width: 4 floats (slower), 8 floats (BEST), 16 floats (L1
//    pressure + occupancy drop, -2us).
//  - input load policy: .cs (BEST), evict_last pinning (regressed twice —
//    hint can't defend 41-102 MB against the stream), .cv (catastrophic:
//    -10us, kills intra-replay L2 sector coalescing).
//  - load width: 2x128-bit __ldcs (BEST), 1x256-bit .cs (lost retention win).
//  - output store: .cs (good), L2::evict_last.v4.b64 (BEST, ~2.2us win:
//    dirty output lines survive graph replays, overwritten in L2 before
//    costing DRAM writebacks; sm_103a encodes evict hints on 256-bit forms
//    only; 32B-aligned since t % 8 == 0).
//  - CTA shape: 256 (BEST/tied), 512 (neutral).
// Operating point: ~180 MB/replay DRAM traffic vs 164 MB mandatory-read
// floor (each input element is read exactly once — no further reduction
// exists); ~6.1 TB/s achieved on a fully coalesced stream.

namespace {
constexpr int NF = 4000;
constexpr int FS = 320;
constexpr int SHIFT = 160;
constexpr int SIG_LEN = (NF - 1) * SHIFT + FS;     // 640160
constexpr int OCTS_PER_BATCH = SIG_LEN / 8;        // 80020
constexpr int FRAME_VECS = FS / 4;                 // 80
constexpr int THREADS = 256;
}

__device__ __forceinline__ unsigned long long pack2(float lo, float hi) {
    return (unsigned long long)__float_as_uint(lo)
         | ((unsigned long long)__float_as_uint(hi) << 32);
}

__device__ __forceinline__ void st_oct_evict_last(float4* p,
                                                  const float4& a, const float4& b) {
    unsigned long long d0 = pack2(a.x, a.y);
    unsigned long long d1 = pack2(a.z, a.w);
    unsigned long long d2 = pack2(b.x, b.y);
    unsigned long long d3 = pack2(b.z, b.w);
    asm volatile("st.global.L2::evict_last.v4.b64 [%0], {%1,%2,%3,%4};"
                 :: "l"(p), "l"(d0), "l"(d1), "l"(d2), "l"(d3)
                 : "memory");
}

__global__ void __launch_bounds__(THREADS)
ola_kernel(const float4* __restrict__ in, float4* __restrict__ out) {
    const int to = blockIdx.x * THREADS + threadIdx.x;  // oct index within batch
    if (to >= OCTS_PER_BATCH) return;
    const int b = blockIdx.y;

    const int t = to * 8;
    const unsigned f1 = (unsigned)t / (unsigned)SHIFT;   // 0..NF
    const int off = t - (int)f1 * SHIFT;                 // multiple of 8, [0,152]
    const int v = off >> 2;

    const float4* __restrict__ base = in + (size_t)b * (size_t)(NF * FRAME_VECS);

    float4 a0 = make_float4(0.f, 0.f, 0.f, 0.f);
    float4 a1 = a0;
    float scale = 0.5f;

    if (f1 < NF) {
        const float4* p = base + (size_t)f1 * FRAME_VECS + v;
        a0 = __ldcs(p);
        a1 = __ldcs(p + 1);
    } else {
        scale = 1.0f;   // tail: only frame NF-1 contributes
    }
    if (f1 > 0) {
        const float4* p = base + (size_t)(f1 - 1) * FRAME_VECS + v + (SHIFT >> 2);
        const float4 c0 = __ldcs(p);
        const float4 c1 = __ldcs(p + 1);
        a0.x += c0.x; a0.y += c0.y; a0.z += c0.z; a0.w += c0.w;
        a1.x += c1.x; a1.y += c1.y; a1.z += c1.z; a1.w += c1.w;
    } else {
        scale = 1.0f;   // head: only frame 0 contributes
    }

    a0.x *= scale; a0.y *= scale; a0.z *= scale; a0.w *= scale;
    a1.x *= scale; a1.y *= scale; a1.z *= scale; a1.w *= scale;

    float4* o = out + (size_t)b * (OCTS_PER_BATCH * 2) + (size_t)to * 2;
    st_oct_evict_last(o, a0, a1);
}

extern "C" void kernel_launch(void* const* d_in, const int* in_sizes, int n_in,
                              void* d_out, int out_size) {
    const float4* in = (const float4*)d_in[0];
    float4* out = (float4*)d_out;

    const int B = in_sizes[0] / (NF * FS);

    dim3 grid((OCTS_PER_BATCH + THREADS - 1) / THREADS, B, 1);
    ola_kernel<<<grid, THREADS>>>(in, out);
}